// round 1
// baseline (speedup 1.0000x reference)
#include <cuda_runtime.h>
#include <cstdint>

#define B_    16
#define C_    3
#define H_    512
#define W_    512
#define HW_   (H_ * W_)
#define NCLS  64
#define NSEG  (B_ * NCLS)

// Persistent accumulators. Zero-initialized at module load; finalize_kernel
// restores them to zero at the end of every launch, so each replay of the
// captured graph sees zeroed bins (deterministic, allocation-free).
__device__ float d_sums[NSEG];
__device__ int   d_cnts[NSEG];

// Fixed-point packing for the fused (count, sum) shared atomic:
//   bits [44:64) : pixel count   (max 4096/block-bin << 2^20)
//   bits [ 0:44) : sum * 2^22    (max ~4096*40*2^22 ≈ 6.9e11 << 2^44)
#define SUM_SCALE     4194304.0f          /* 2^22 */
#define SUM_INV_SCALE (1.0f / 4194304.0f)
#define CNT_ONE       (1ull << 44)
#define SUM_MASK      ((1ull << 44) - 1ull)

// Pass 1: one sweep over input/target/mask. Each block handles 1024 float4
// vectors (4096 pixels) of one batch image. Per-pixel channel-sum of |in-tgt|
// goes into a 64-entry shared histogram via ONE packed 64-bit atomicAdd,
// then the block flushes 64 bins to the global (batch,class) accumulators.
__global__ void __launch_bounds__(256)
pass1_kernel(const float* __restrict__ inp,
             const float* __restrict__ tgt,
             const int*   __restrict__ msk)
{
    __shared__ unsigned long long bins[NCLS];
    const int t = threadIdx.x;
    if (t < NCLS) bins[t] = 0ull;
    __syncthreads();

    const int b        = blockIdx.y;
    const int vec_base = blockIdx.x * 1024;           // 64 blocks/batch * 1024 vecs
    const int HW4      = HW_ / 4;

    const float4* ip = (const float4*)(inp + (size_t)b * C_ * HW_);
    const float4* tp = (const float4*)(tgt + (size_t)b * C_ * HW_);
    const int4*   mp = (const int4*)  (msk + (size_t)b * HW_);

#pragma unroll
    for (int it = 0; it < 4; it++) {
        const int v = vec_base + it * 256 + t;

        const float4 a0 = __ldg(ip + v);
        const float4 a1 = __ldg(ip + HW4 + v);
        const float4 a2 = __ldg(ip + 2 * HW4 + v);
        const float4 c0 = __ldg(tp + v);
        const float4 c1 = __ldg(tp + HW4 + v);
        const float4 c2 = __ldg(tp + 2 * HW4 + v);
        const int4   m  = __ldg(mp + v);

        const float w0 = fabsf(a0.x - c0.x) + fabsf(a1.x - c1.x) + fabsf(a2.x - c2.x);
        const float w1 = fabsf(a0.y - c0.y) + fabsf(a1.y - c1.y) + fabsf(a2.y - c2.y);
        const float w2 = fabsf(a0.z - c0.z) + fabsf(a1.z - c1.z) + fabsf(a2.z - c2.z);
        const float w3 = fabsf(a0.w - c0.w) + fabsf(a1.w - c1.w) + fabsf(a2.w - c2.w);

        atomicAdd(&bins[m.x & (NCLS - 1)], CNT_ONE + __float2ull_rn(w0 * SUM_SCALE));
        atomicAdd(&bins[m.y & (NCLS - 1)], CNT_ONE + __float2ull_rn(w1 * SUM_SCALE));
        atomicAdd(&bins[m.z & (NCLS - 1)], CNT_ONE + __float2ull_rn(w2 * SUM_SCALE));
        atomicAdd(&bins[m.w & (NCLS - 1)], CNT_ONE + __float2ull_rn(w3 * SUM_SCALE));
    }
    __syncthreads();

    if (t < NCLS) {
        const unsigned long long p = bins[t];
        const unsigned int cnt = (unsigned int)(p >> 44);
        if (cnt) {
            const float s = (float)(p & SUM_MASK) * SUM_INV_SCALE;
            atomicAdd(&d_sums[b * NCLS + t], s);
            atomicAdd(&d_cnts[b * NCLS + t], (int)cnt);
        }
    }
}

// Finalize: 1024 threads, one per (batch,class) segment.
//   avg[r]  = sums[r] / max(cnts[r]*C, 1)
//   result  = ( sum_r sums[r]  +  BETA * sum_r sums[r]*avg[r] / max_r avg[r] ) / N
// (weight/max is in [0,1] so the reference clip is a no-op; empty regions
//  have avg=0 and cannot be the max when any data exists.)
__global__ void __launch_bounds__(1024)
finalize_kernel(float* __restrict__ out)
{
    const int t = threadIdx.x;

    const float s = d_sums[t];
    const int   c = d_cnts[t];
    // reset for the next graph replay
    d_sums[t] = 0.0f;
    d_cnts[t] = 0;

    const float avg = s / fmaxf((float)c * (float)C_, 1.0f);
    float mx  = avg;
    float tot = s;
    float ws  = s * avg;

    // intra-warp reduce
#pragma unroll
    for (int o = 16; o > 0; o >>= 1) {
        mx  = fmaxf(mx, __shfl_xor_sync(0xffffffffu, mx, o));
        tot += __shfl_xor_sync(0xffffffffu, tot, o);
        ws  += __shfl_xor_sync(0xffffffffu, ws, o);
    }

    __shared__ float smx[32], stot[32], sws[32];
    const int lane = t & 31, wid = t >> 5;
    if (lane == 0) { smx[wid] = mx; stot[wid] = tot; sws[wid] = ws; }
    __syncthreads();

    if (wid == 0) {
        mx  = smx[lane];
        tot = stot[lane];
        ws  = sws[lane];
#pragma unroll
        for (int o = 16; o > 0; o >>= 1) {
            mx  = fmaxf(mx, __shfl_xor_sync(0xffffffffu, mx, o));
            tot += __shfl_xor_sync(0xffffffffu, tot, o);
            ws  += __shfl_xor_sync(0xffffffffu, ws, o);
        }
        if (lane == 0) {
            const float N = (float)B_ * (float)C_ * (float)HW_;
            const float weighted = (mx > 0.0f) ? (ws / mx) : 0.0f;  // BETA = 1
            out[0] = (tot + weighted) / N;
        }
    }
}

extern "C" void kernel_launch(void* const* d_in, const int* in_sizes, int n_in,
                              void* d_out, int out_size)
{
    const float* inp = (const float*)d_in[0];
    const float* tgt = (const float*)d_in[1];
    const int*   msk = (const int*)  d_in[2];
    (void)in_sizes; (void)n_in; (void)out_size;

    pass1_kernel<<<dim3(64, B_), 256>>>(inp, tgt, msk);
    finalize_kernel<<<1, 1024>>>((float*)d_out);
}